// round 6
// baseline (speedup 1.0000x reference)
#include <cuda_runtime.h>
#include <cuda_bf16.h>
#include <cstdint>

// Problem dims (fixed)
#define BB 4
#define TT 4096
#define EE 1024
#define HH 64
#define BT (BB * TT)          // 16384 rows
#define SCALE 0.03125f        // E^-0.5

// Scratch (device globals)
__device__ float g_M[BB * HH * HH];                 // per-batch K^T V (fp32)
__device__ float g_c[BB * HH];                      // per-batch scale*(bq @ M)
__device__ __nv_bfloat16 g_WT_hi[128 * EE];         // [n][k]: n 0-63 = Wk, 64-127 = Wv
__device__ __nv_bfloat16 g_WT_lo[128 * EE];
__device__ __nv_bfloat16 g_Wp_hi[BB * HH * EE];     // W'' transposed [b][n][k]
__device__ __nv_bfloat16 g_Wp_lo[BB * HH * EE];

// ---------------------------------------------------------------------------
// mma.sync bf16 (baseline PTX — works under compute_103 target)
// ---------------------------------------------------------------------------
#define MMA_BF16(c, a, b)                                                     \
    asm volatile(                                                             \
        "mma.sync.aligned.m16n8k16.row.col.f32.bf16.bf16.f32 "                \
        "{%0,%1,%2,%3}, {%4,%5,%6,%7}, {%8,%9}, {%0,%1,%2,%3};\n"             \
        : "+f"(c[0]), "+f"(c[1]), "+f"(c[2]), "+f"(c[3])                      \
        : "r"(a[0]), "r"(a[1]), "r"(a[2]), "r"(a[3]), "r"(b[0]), "r"(b[1]))

__device__ __forceinline__ void split_bf16(float v, __nv_bfloat16& hi, __nv_bfloat16& lo) {
    hi = __float2bfloat16_rn(v);
    lo = __float2bfloat16_rn(v - __bfloat162float(hi));
}

// ---------------------------------------------------------------------------
// Prep: split Wk|Wv (fp32 [k][n]) -> bf16 hi/lo transposed [n][k]
// ---------------------------------------------------------------------------
__global__ void prep_w_kernel(const float* __restrict__ Wk,
                              const float* __restrict__ Wv)
{
    int i = blockIdx.x * blockDim.x + threadIdx.x;
    if (i >= 128 * EE) return;
    int n = i % 128;
    int k = i / 128;
    const float* W = (n >= 64) ? Wv : Wk;
    float v = W[k * HH + (n & 63)];
    __nv_bfloat16 hi, lo;
    split_bf16(v, hi, lo);
    g_WT_hi[(size_t)n * EE + k] = hi;
    g_WT_lo[(size_t)n * EE + k] = lo;
}

__global__ void zero_m_kernel()
{
    int i = blockIdx.x * blockDim.x + threadIdx.x;
    if (i < BB * HH * HH) g_M[i] = 0.f;
}

// ---------------------------------------------------------------------------
// kv_fused: per block compute K,V for 64 rows (bf16x3 HMMA) then fold the
// partial K^T V into g_M via atomics. grid = BT/64 = 256, 256 threads.
// 8 warps: wm = warp>>2 (2 x 32 rows), wn = warp&3 (4 x 32 cols; n<64=K, else V)
// ---------------------------------------------------------------------------
__global__ __launch_bounds__(256) void kv_fused_kernel(
    const float* __restrict__ X,
    const float* __restrict__ bk,
    const float* __restrict__ bv)
{
    __shared__ __align__(16) char pool[34816];
    __nv_bfloat16 (*Xh)[40] = (__nv_bfloat16(*)[40])(pool);          //  5120 B
    __nv_bfloat16 (*Xl)[40] = (__nv_bfloat16(*)[40])(pool + 5120);   //  5120 B
    __nv_bfloat16 (*Wh)[40] = (__nv_bfloat16(*)[40])(pool + 10240);  // 10240 B
    __nv_bfloat16 (*Wl)[40] = (__nv_bfloat16(*)[40])(pool + 20480);  // 10240 B

    const int t    = threadIdx.x;
    const int warp = t >> 5;
    const int lane = t & 31;
    const int g    = lane >> 2;
    const int tig  = lane & 3;
    const int wm   = warp >> 2;      // 0..1
    const int wn   = warp & 3;       // 0..3
    const int m0   = blockIdx.x * 64;
    const int batch = m0 >> 12;      // 4096 rows per batch, 64 | 4096

    const float4* X4 = (const float4*)X;

    float c[2][4][4];
#pragma unroll
    for (int mt = 0; mt < 2; mt++)
#pragma unroll
        for (int nt = 0; nt < 4; nt++)
#pragma unroll
            for (int j = 0; j < 4; j++) c[mt][nt][j] = 0.f;

    for (int k0 = 0; k0 < EE; k0 += 32) {
        // X tile: 64 rows x 32 cols fp32 -> split bf16 (512 float4, 2/thread)
#pragma unroll
        for (int l = 0; l < 2; l++) {
            int f   = t + l * 256;
            int row = f >> 3;
            int c4  = f & 7;
            float4 v = X4[(size_t)(m0 + row) * (EE / 4) + (k0 >> 2) + c4];
            float vv[4] = {v.x, v.y, v.z, v.w};
            __nv_bfloat16 hb[4], lb[4];
#pragma unroll
            for (int j = 0; j < 4; j++) split_bf16(vv[j], hb[j], lb[j]);
            uint2 hp, lp;
            hp.x = ((uint32_t)__bfloat16_as_ushort(hb[1]) << 16) | __bfloat16_as_ushort(hb[0]);
            hp.y = ((uint32_t)__bfloat16_as_ushort(hb[3]) << 16) | __bfloat16_as_ushort(hb[2]);
            lp.x = ((uint32_t)__bfloat16_as_ushort(lb[1]) << 16) | __bfloat16_as_ushort(lb[0]);
            lp.y = ((uint32_t)__bfloat16_as_ushort(lb[3]) << 16) | __bfloat16_as_ushort(lb[2]);
            *(uint2*)&Xh[row][c4 * 4] = hp;
            *(uint2*)&Xl[row][c4 * 4] = lp;
        }
        // W tiles: 128 n-rows x 32 k bf16 per plane (512 uint4/plane, 2/thread)
#pragma unroll
        for (int l = 0; l < 4; l++) {
            int f = t + l * 256;         // 0..1023
            int plane = (f >= 512);
            int ff = f & 511;
            int row = ff >> 2;           // 0..127
            int ch  = ff & 3;            // 0..3 (8 bf16 = 16B each)
            const __nv_bfloat16* src =
                (plane ? g_WT_lo : g_WT_hi) + (size_t)row * EE + k0 + ch * 8;
            uint4 v = *(const uint4*)src;
            if (plane) *(uint4*)&Wl[row][ch * 8] = v;
            else       *(uint4*)&Wh[row][ch * 8] = v;
        }
        __syncthreads();

#pragma unroll
        for (int ks = 0; ks < 2; ks++) {
            const int kb = ks * 16;
            uint32_t ah[2][4], al[2][4];
#pragma unroll
            for (int mt = 0; mt < 2; mt++) {
                int r = wm * 32 + mt * 16 + g;
                ah[mt][0] = *(const uint32_t*)&Xh[r][kb + 2 * tig];
                ah[mt][1] = *(const uint32_t*)&Xh[r + 8][kb + 2 * tig];
                ah[mt][2] = *(const uint32_t*)&Xh[r][kb + 2 * tig + 8];
                ah[mt][3] = *(const uint32_t*)&Xh[r + 8][kb + 2 * tig + 8];
                al[mt][0] = *(const uint32_t*)&Xl[r][kb + 2 * tig];
                al[mt][1] = *(const uint32_t*)&Xl[r + 8][kb + 2 * tig];
                al[mt][2] = *(const uint32_t*)&Xl[r][kb + 2 * tig + 8];
                al[mt][3] = *(const uint32_t*)&Xl[r + 8][kb + 2 * tig + 8];
            }
            uint32_t bh[4][2], bl[4][2];
#pragma unroll
            for (int nt = 0; nt < 4; nt++) {
                int n = wn * 32 + nt * 8 + g;
                bh[nt][0] = *(const uint32_t*)&Wh[n][kb + 2 * tig];
                bh[nt][1] = *(const uint32_t*)&Wh[n][kb + 2 * tig + 8];
                bl[nt][0] = *(const uint32_t*)&Wl[n][kb + 2 * tig];
                bl[nt][1] = *(const uint32_t*)&Wl[n][kb + 2 * tig + 8];
            }
#pragma unroll
            for (int mt = 0; mt < 2; mt++)
#pragma unroll
                for (int nt = 0; nt < 4; nt++) {
                    MMA_BF16(c[mt][nt], ah[mt], bh[nt]);
                    MMA_BF16(c[mt][nt], ah[mt], bl[nt]);
                    MMA_BF16(c[mt][nt], al[mt], bh[nt]);
                }
        }
        __syncthreads();
    }

    // --- epilogue: bias, stage K/V tiles, partial outer product, atomics ---
    float* Ks = (float*)pool;            // [64][68]
    float* Vs = (float*)(pool + 17408);  // [64][68]
    // (mainloop smem reads all complete: last __syncthreads above)
#pragma unroll
    for (int mt = 0; mt < 2; mt++) {
        int r = wm * 32 + mt * 16 + g;
#pragma unroll
        for (int nt = 0; nt < 4; nt++) {
            int nbase = wn * 32 + nt * 8;
            int which = nbase >> 6;              // 0 = K, 1 = V
            int nc    = (nbase & 63) + 2 * tig;
            const float* bias = which ? bv : bk;
            float* S = which ? Vs : Ks;
            float b0v = bias[nc];
            float b1v = bias[nc + 1];
            S[r * 68 + nc]           = c[mt][nt][0] + b0v;
            S[r * 68 + nc + 1]       = c[mt][nt][1] + b1v;
            S[(r + 8) * 68 + nc]     = c[mt][nt][2] + b0v;
            S[(r + 8) * 68 + nc + 1] = c[mt][nt][3] + b1v;
        }
    }
    __syncthreads();

    {
        const int i0 = (t >> 4) * 4;    // h1
        const int j0 = (t & 15) * 4;    // h2
        float acc[4][4];
#pragma unroll
        for (int i = 0; i < 4; i++)
#pragma unroll
            for (int j = 0; j < 4; j++) acc[i][j] = 0.f;
#pragma unroll 8
        for (int s = 0; s < 64; s++) {
            float4 kk = *(const float4*)&Ks[s * 68 + i0];
            float4 vv = *(const float4*)&Vs[s * 68 + j0];
            float a[4] = {kk.x, kk.y, kk.z, kk.w};
            float b2[4] = {vv.x, vv.y, vv.z, vv.w};
#pragma unroll
            for (int i = 0; i < 4; i++)
#pragma unroll
                for (int j = 0; j < 4; j++)
                    acc[i][j] += a[i] * b2[j];
        }
        float* Mb = g_M + (size_t)batch * HH * HH;
#pragma unroll
        for (int i = 0; i < 4; i++)
#pragma unroll
            for (int j = 0; j < 4; j++)
                atomicAdd(&Mb[(i0 + i) * HH + j0 + j], acc[i][j]);
    }
}

// ---------------------------------------------------------------------------
// wprime: W''_b = SCALE * Wq @ M_b  -> bf16 hi/lo transposed [b][n][k];
//         c_b  = SCALE * bq @ M_b.
// grid (16, BB): block covers 64 e-rows of Wq for one batch. 256 threads.
// ---------------------------------------------------------------------------
__global__ __launch_bounds__(256) void wprime_kernel(
    const float* __restrict__ Wq,
    const float* __restrict__ bq)
{
    __shared__ float Ms[64][65];          // 16640 B
    __shared__ unsigned short Wth[64][66];
    __shared__ unsigned short Wtl[64][66];

    const int t  = threadIdx.x;
    const int b  = blockIdx.y;
    const int r0 = blockIdx.x * 64;

    // load M_b (4096 floats, 16/thread, coalesced)
#pragma unroll
    for (int l = 0; l < 16; l++) {
        int f = t + l * 256;
        Ms[f >> 6][f & 63] = g_M[(size_t)b * HH * HH + f];
    }
    __syncthreads();

    // compute 16 outputs per thread: row i = t>>2 (e-local), cols j0..j0+15
    const int i  = t >> 2;
    const int j0 = (t & 3) * 16;
    const int e  = r0 + i;
    float acc[16];
#pragma unroll
    for (int j = 0; j < 16; j++) acc[j] = 0.f;
    for (int k = 0; k < 64; k++) {
        float w = Wq[(size_t)e * HH + k];
#pragma unroll
        for (int j = 0; j < 16; j++)
            acc[j] += w * Ms[k][j0 + j];
    }
#pragma unroll
    for (int j = 0; j < 16; j++) {
        float v = acc[j] * SCALE;
        __nv_bfloat16 hi, lo;
        split_bf16(v, hi, lo);
        Wth[j0 + j][i] = __bfloat16_as_ushort(hi);
        Wtl[j0 + j][i] = __bfloat16_as_ushort(lo);
    }

    // c_b (only one block per batch does it)
    if (blockIdx.x == 0 && t < 64) {
        float a = 0.f;
        for (int k = 0; k < 64; k++)
            a += bq[k] * Ms[k][t];
        g_c[b * HH + t] = a * SCALE;
    }
    __syncthreads();

    // coalesced store of transposed planes (uint = 2 bf16 per store)
#pragma unroll
    for (int l = 0; l < 8; l++) {
        int f = t + l * 256;              // 0..2047
        int n = f >> 5;                   // 0..63
        int e2 = (f & 31) * 2;            // 0..62 even
        uint32_t hv = (uint32_t)Wth[n][e2] | ((uint32_t)Wth[n][e2 + 1] << 16);
        uint32_t lv = (uint32_t)Wtl[n][e2] | ((uint32_t)Wtl[n][e2 + 1] << 16);
        size_t off = (size_t)b * HH * EE + (size_t)n * EE + r0 + e2;
        *(uint32_t*)(g_Wp_hi + off) = hv;
        *(uint32_t*)(g_Wp_lo + off) = lv;
    }
}

// ---------------------------------------------------------------------------
// out_gemm: out = X @ W''_b + c_b. M=16384, N=64, K=1024. grid = BT/128 = 128
// (single wave). 8 warps: wm = warp>>1 (4 x 32 rows), wn = warp&1 (2 x 32 cols)
// ---------------------------------------------------------------------------
__global__ __launch_bounds__(256) void out_mma_kernel(
    const float* __restrict__ X,
    float* __restrict__ out)
{
    __shared__ __nv_bfloat16 Xh[128][40];
    __shared__ __nv_bfloat16 Xl[128][40];
    __shared__ __nv_bfloat16 Wh[64][40];
    __shared__ __nv_bfloat16 Wl[64][40];

    const int t    = threadIdx.x;
    const int warp = t >> 5;
    const int lane = t & 31;
    const int g    = lane >> 2;
    const int tig  = lane & 3;
    const int wm   = warp >> 1;      // 0..3
    const int wn   = warp & 1;       // 0..1
    const int m0   = blockIdx.x * 128;
    const int batch = m0 >> 12;

    const float4* X4 = (const float4*)X;
    const __nv_bfloat16* Wph = g_Wp_hi + (size_t)batch * HH * EE;
    const __nv_bfloat16* Wpl = g_Wp_lo + (size_t)batch * HH * EE;

    float c[2][4][4];
#pragma unroll
    for (int mt = 0; mt < 2; mt++)
#pragma unroll
        for (int nt = 0; nt < 4; nt++)
#pragma unroll
            for (int j = 0; j < 4; j++) c[mt][nt][j] = 0.f;

    for (int k0 = 0; k0 < EE; k0 += 32) {
        // X tile: 128 x 32 (1024 float4, 4/thread)
#pragma unroll
        for (int l = 0; l < 4; l++) {
            int f   = t + l * 256;
            int row = f >> 3;
            int c4  = f & 7;
            float4 v = X4[(size_t)(m0 + row) * (EE / 4) + (k0 >> 2) + c4];
            float vv[4] = {v.x, v.y, v.z, v.w};
            __nv_bfloat16 hb[4], lb[4];
#pragma unroll
            for (int j = 0; j < 4; j++) split_bf16(vv[j], hb[j], lb[j]);
            uint2 hp, lp;
            hp.x = ((uint32_t)__bfloat16_as_ushort(hb[1]) << 16) | __bfloat16_as_ushort(hb[0]);
            hp.y = ((uint32_t)__bfloat16_as_ushort(hb[3]) << 16) | __bfloat16_as_ushort(hb[2]);
            lp.x = ((uint32_t)__bfloat16_as_ushort(lb[1]) << 16) | __bfloat16_as_ushort(lb[0]);
            lp.y = ((uint32_t)__bfloat16_as_ushort(lb[3]) << 16) | __bfloat16_as_ushort(lb[2]);
            *(uint2*)&Xh[row][c4 * 4] = hp;
            *(uint2*)&Xl[row][c4 * 4] = lp;
        }
        // W'' tiles: 64 n-rows x 32 k per plane (256 uint4/plane, 2/thread total)
        {
            int f = t;                   // 0..255
            int plane = (f >= 256) ? 1 : 0; (void)plane;
            int row = (f >> 2) & 63;     // 0..63
            int ch  = f & 3;
            *(uint4*)&Wh[row][ch * 8] = *(const uint4*)(Wph + (size_t)row * EE + k0 + ch * 8);
            *(uint4*)&Wl[row][ch * 8] = *(const uint4*)(Wpl + (size_t)row * EE + k0 + ch * 8);
        }
        __syncthreads();

#pragma unroll
        for (int ks = 0; ks < 2; ks++) {
            const int kb = ks * 16;
            uint32_t ah[2][4], al[2][4];
#pragma unroll
            for (int mt = 0; mt < 2; mt++) {
                int r = wm * 32 + mt * 16 + g;
                ah[mt][0] = *(const uint32_t*)&Xh[r][kb + 2 * tig];
                ah[mt][1] = *(const uint32_t*)&Xh[r + 8][kb + 2 * tig];
                ah[mt][2] = *(const uint32_t*)&Xh[r][kb + 2 * tig + 8];
                ah[mt][3] = *(const uint32_t*)&Xh[r + 8][kb + 2 * tig + 8];
                al[mt][0] = *(const uint32_t*)&Xl[r][kb + 2 * tig];
                al[mt][1] = *(const uint32_t*)&Xl[r + 8][kb + 2 * tig];
                al[mt][2] = *(const uint32_t*)&Xl[r][kb + 2 * tig + 8];
                al[mt][3] = *(const uint32_t*)&Xl[r + 8][kb + 2 * tig + 8];
            }
            uint32_t bh[4][2], bl[4][2];
#pragma unroll
            for (int nt = 0; nt < 4; nt++) {
                int n = wn * 32 + nt * 8 + g;
                bh[nt][0] = *(const uint32_t*)&Wh[n][kb + 2 * tig];
                bh[nt][1] = *(const uint32_t*)&Wh[n][kb + 2 * tig + 8];
                bl[nt][0] = *(const uint32_t*)&Wl[n][kb + 2 * tig];
                bl[nt][1] = *(const uint32_t*)&Wl[n][kb + 2 * tig + 8];
            }
#pragma unroll
            for (int mt = 0; mt < 2; mt++)
#pragma unroll
                for (int nt = 0; nt < 4; nt++) {
                    MMA_BF16(c[mt][nt], ah[mt], bh[nt]);
                    MMA_BF16(c[mt][nt], ah[mt], bl[nt]);
                    MMA_BF16(c[mt][nt], al[mt], bh[nt]);
                }
        }
        __syncthreads();
    }

    // epilogue: + c_b, store
    const float* cv = g_c + batch * HH;
#pragma unroll
    for (int mt = 0; mt < 2; mt++) {
        int r0 = m0 + wm * 32 + mt * 16 + g;
#pragma unroll
        for (int nt = 0; nt < 4; nt++) {
            int n = wn * 32 + nt * 8 + 2 * tig;
            float c0 = cv[n];
            float c1 = cv[n + 1];
            float2 o0 = {c[mt][nt][0] + c0, c[mt][nt][1] + c1};
            float2 o1 = {c[mt][nt][2] + c0, c[mt][nt][3] + c1};
            *(float2*)&out[(size_t)r0 * HH + n] = o0;
            *(float2*)&out[(size_t)(r0 + 8) * HH + n] = o1;
        }
    }
}

// ---------------------------------------------------------------------------
// Launch
// ---------------------------------------------------------------------------
extern "C" void kernel_launch(void* const* d_in, const int* in_sizes, int n_in,
                              void* d_out, int out_size)
{
    const float* idx = (const float*)d_in[0];
    const float* Wq  = (const float*)d_in[1];
    const float* bq  = (const float*)d_in[2];
    const float* Wk  = (const float*)d_in[3];
    const float* bk  = (const float*)d_in[4];
    const float* Wv  = (const float*)d_in[5];
    const float* bv  = (const float*)d_in[6];
    float* out = (float*)d_out;

    prep_w_kernel<<<(128 * EE + 255) / 256, 256>>>(Wk, Wv);
    zero_m_kernel<<<(BB * HH * HH + 255) / 256, 256>>>();

    kv_fused_kernel<<<BT / 64, 256>>>(idx, bk, bv);

    wprime_kernel<<<dim3(16, BB), 256>>>(Wq, bq);

    out_mma_kernel<<<BT / 128, 256>>>(idx, out);
}

// round 7
// speedup vs baseline: 1.8987x; 1.8987x over previous
#include <cuda_runtime.h>
#include <cuda_bf16.h>
#include <cstdint>

// Problem dims (fixed)
#define BB 4
#define TT 4096
#define EE 1024
#define HH 64
#define BT (BB * TT)          // 16384 rows
#define SCALE 0.03125f        // E^-0.5

// Scratch (device globals)
__device__ float g_Q[BT * HH];
__device__ float g_K[BT * HH];
__device__ float g_V[BT * HH];
__device__ float g_M[BB * HH * HH];
__device__ __nv_bfloat16 g_WT_hi[192 * EE];   // [n][k]; n: q 0-63, k 64-127, v 128-191
__device__ __nv_bfloat16 g_WT_lo[192 * EE];

// ---------------------------------------------------------------------------
// PTX helpers (all baseline PTX, valid under compute_103)
// ---------------------------------------------------------------------------
#define MMA_BF16(c, a, b)                                                     \
    asm volatile(                                                             \
        "mma.sync.aligned.m16n8k16.row.col.f32.bf16.bf16.f32 "                \
        "{%0,%1,%2,%3}, {%4,%5,%6,%7}, {%8,%9}, {%0,%1,%2,%3};\n"             \
        : "+f"(c[0]), "+f"(c[1]), "+f"(c[2]), "+f"(c[3])                      \
        : "r"(a[0]), "r"(a[1]), "r"(a[2]), "r"(a[3]), "r"(b[0]), "r"(b[1]))

#define LDSM4(r0, r1, r2, r3, addr)                                           \
    asm volatile("ldmatrix.sync.aligned.m8n8.x4.shared.b16 {%0,%1,%2,%3}, [%4];" \
        : "=r"(r0), "=r"(r1), "=r"(r2), "=r"(r3) : "r"(addr))

#define CP_ASYNC16(dst, src) \
    asm volatile("cp.async.cg.shared.global [%0], [%1], 16;" :: "r"(dst), "l"(src))
#define CP_COMMIT() asm volatile("cp.async.commit_group;")
#define CP_WAIT0()  asm volatile("cp.async.wait_group 0;")

__device__ __forceinline__ uint32_t smem_u32(const void* p) {
    uint32_t a;
    asm("{ .reg .u64 t; cvta.to.shared.u64 t, %1; cvt.u32.u64 %0, t; }" : "=r"(a) : "l"(p));
    return a;
}

__device__ __forceinline__ void split_bf16(float v, __nv_bfloat16& hi, __nv_bfloat16& lo) {
    hi = __float2bfloat16_rn(v);
    lo = __float2bfloat16_rn(v - __bfloat162float(hi));
}

// ---------------------------------------------------------------------------
// Prep: zero g_M + split Wq|Wk|Wv (fp32 [k][n]) -> bf16 hi/lo transposed [n][k]
// ---------------------------------------------------------------------------
__global__ void prep_kernel(const float* __restrict__ Wq,
                            const float* __restrict__ Wk,
                            const float* __restrict__ Wv)
{
    int i = blockIdx.x * blockDim.x + threadIdx.x;
    if (i < BB * HH * HH) g_M[i] = 0.f;
    if (i >= 192 * EE) return;
    int n = i % 192;
    int k = i / 192;
    const float* W = (n < 64) ? Wq : ((n < 128) ? Wk : Wv);
    float v = W[k * HH + (n & 63)];
    __nv_bfloat16 hi, lo;
    split_bf16(v, hi, lo);
    g_WT_hi[(size_t)n * EE + k] = hi;
    g_WT_lo[(size_t)n * EE + k] = lo;
}

// ---------------------------------------------------------------------------
// QKV projection via bf16x3 mma.sync, ldmatrix fragments, cp.async W tiles,
// double-buffered BK=32. grid = (BT/128, 3), 256 threads = 8 warps (4M x 2N),
// warp tile 32(M) x 32(N).
//
// Dynamic smem per buffer (stride 30720B):
//   Xh [128][40]b16 @ 0      (10240)
//   Xl [128][40]    @ 10240  (10240)
//   Wh [ 64][40]    @ 20480  ( 5120)
//   Wl [ 64][40]    @ 25600  ( 5120)
// Two buffers = 61440 B.
// ---------------------------------------------------------------------------
#define BUFS 30720
#define QKV_SMEM (2 * BUFS)

__global__ __launch_bounds__(256) void qkv_mma_kernel(
    const float* __restrict__ X,
    const float* __restrict__ bq,
    const float* __restrict__ bkk,
    const float* __restrict__ bv)
{
    extern __shared__ __align__(16) char sm[];
    const uint32_t sb = smem_u32(sm);
    const int t    = threadIdx.x;
    const int warp = t >> 5;
    const int lane = t & 31;
    const int g    = lane >> 2;
    const int tig  = lane & 3;
    const int wm   = warp >> 1;      // 0..3 -> m offset 32*wm
    const int wn   = warp & 1;       // 0..1 -> n offset 32*wn
    const int m0   = blockIdx.x * 128;
    const int which = blockIdx.y;

    const float4* X4 = (const float4*)X;
    const __nv_bfloat16* WHp = g_WT_hi + (size_t)which * 64 * EE;
    const __nv_bfloat16* WLp = g_WT_lo + (size_t)which * 64 * EE;

    float c[2][4][4];
#pragma unroll
    for (int mt = 0; mt < 2; mt++)
#pragma unroll
        for (int nt = 0; nt < 4; nt++)
#pragma unroll
            for (int j = 0; j < 4; j++) c[mt][nt][j] = 0.f;

    float4 xr[4];
    const int xrow = t >> 3;         // 0..31 (4 rows per thread, stride 32)
    const int xc4  = t & 7;          // float4 chunk within 32-col tile

    // prefetch X tile (k0) into registers
    auto ldgX = [&](int k0) {
#pragma unroll
        for (int j = 0; j < 4; j++)
            xr[j] = X4[(size_t)(m0 + xrow + j * 32) * (EE / 4) + (k0 >> 2) + xc4];
    };
    // convert + store X registers -> buffer
    auto stX = [&](int buf) {
        char* xh = sm + buf * BUFS;
        char* xl = xh + 10240;
#pragma unroll
        for (int j = 0; j < 4; j++) {
            float vv[4] = {xr[j].x, xr[j].y, xr[j].z, xr[j].w};
            uint32_t hw[2], lw[2];
#pragma unroll
            for (int h = 0; h < 2; h++) {
                __nv_bfloat16 h0, l0, h1, l1;
                split_bf16(vv[2 * h], h0, l0);
                split_bf16(vv[2 * h + 1], h1, l1);
                hw[h] = ((uint32_t)__bfloat16_as_ushort(h1) << 16) | __bfloat16_as_ushort(h0);
                lw[h] = ((uint32_t)__bfloat16_as_ushort(l1) << 16) | __bfloat16_as_ushort(l0);
            }
            int off = (xrow + j * 32) * 80 + xc4 * 8;
            *(uint2*)(xh + off) = make_uint2(hw[0], hw[1]);
            *(uint2*)(xl + off) = make_uint2(lw[0], lw[1]);
        }
    };
    // async-copy W tile (k0) -> buffer (hi+lo planes, 512 x 16B, 2 per thread)
    auto cpW = [&](int k0, int buf) {
        uint32_t wbase = sb + buf * BUFS + 20480;
#pragma unroll
        for (int j = 0; j < 2; j++) {
            int cc = t + j * 256;          // 0..511
            int plane = cc >> 8;           // 0 hi, 1 lo
            int c2 = cc & 255;
            int row = c2 >> 2;             // 0..63
            int q = c2 & 3;                // 16B chunk within 64B row
            const __nv_bfloat16* src = (plane ? WLp : WHp) + (size_t)row * EE + k0 + q * 8;
            uint32_t dst = wbase + plane * 5120 + row * 80 + q * 16;
            CP_ASYNC16(dst, src);
        }
    };
    // 2 ks-steps of 16: ldmatrix fragments + 36 MMAs
    auto domma = [&](int buf) {
        uint32_t xh = sb + buf * BUFS;
#pragma unroll
        for (int ks = 0; ks < 2; ks++) {
            const int kboff = ks * 32;     // bytes: kb*2
            uint32_t ah[2][4], al[2][4], bh[4][2], bl[4][2];
#pragma unroll
            for (int mt = 0; mt < 2; mt++) {
                uint32_t addr = xh + (uint32_t)((wm * 32 + mt * 16 + (lane & 15)) * 80
                                                + kboff + (lane >> 4) * 16);
                LDSM4(ah[mt][0], ah[mt][1], ah[mt][2], ah[mt][3], addr);
                LDSM4(al[mt][0], al[mt][1], al[mt][2], al[mt][3], addr + 10240);
            }
#pragma unroll
            for (int nb = 0; nb < 2; nb++) {
                uint32_t addr = xh + 20480 + (uint32_t)((wn * 32 + nb * 16 + (lane & 15)) * 80
                                                        + kboff + (lane >> 4) * 16);
                uint32_t r0, r1, r2, r3;
                LDSM4(r0, r1, r2, r3, addr);
                bh[nb * 2][0] = r0; bh[nb * 2][1] = r2;
                bh[nb * 2 + 1][0] = r1; bh[nb * 2 + 1][1] = r3;
                LDSM4(r0, r1, r2, r3, addr + 5120);
                bl[nb * 2][0] = r0; bl[nb * 2][1] = r2;
                bl[nb * 2 + 1][0] = r1; bl[nb * 2 + 1][1] = r3;
            }
#pragma unroll
            for (int mt = 0; mt < 2; mt++)
#pragma unroll
                for (int nt = 0; nt < 4; nt++) {
                    MMA_BF16(c[mt][nt], ah[mt], bh[nt]);   // hi*hi
                    MMA_BF16(c[mt][nt], ah[mt], bl[nt]);   // hi*lo
                    MMA_BF16(c[mt][nt], al[mt], bh[nt]);   // lo*hi
                }
        }
    };

    // ---- pipelined mainloop: 32 tiles of BK=32 ----
    ldgX(0);
    cpW(0, 0);
    CP_COMMIT();
    stX(0);
    for (int i = 0; i < 32; i++) {
        int buf = i & 1;
        CP_WAIT0();
        __syncthreads();
        if (i < 31) {
            ldgX((i + 1) * 32);
            cpW((i + 1) * 32, buf ^ 1);
            CP_COMMIT();
        }
        domma(buf);
        if (i < 31) stX(buf ^ 1);
    }

    // ---- epilogue: bias + store fp32 ----
    const float* bias = (which == 0) ? bq : (which == 1) ? bkk : bv;
    float* __restrict__ outp = (which == 0) ? g_Q : (which == 1) ? g_K : g_V;
#pragma unroll
    for (int mt = 0; mt < 2; mt++) {
        int r0 = m0 + wm * 32 + mt * 16 + g;
#pragma unroll
        for (int nt = 0; nt < 4; nt++) {
            int n = wn * 32 + nt * 8 + 2 * tig;
            float b0v = bias[n];
            float b1v = bias[n + 1];
            float2 o0 = {c[mt][nt][0] + b0v, c[mt][nt][1] + b1v};
            float2 o1 = {c[mt][nt][2] + b0v, c[mt][nt][3] + b1v};
            *(float2*)&outp[(size_t)r0 * HH + n] = o0;
            *(float2*)&outp[(size_t)(r0 + 8) * HH + n] = o1;
        }
    }
}

// ---------------------------------------------------------------------------
// M[b] += K[b]^T @ V[b]; CS=32 -> grid (128, 4) = 512 blocks.
// ---------------------------------------------------------------------------
#define CS 32
__global__ __launch_bounds__(256) void kv_outer_kernel()
{
    __shared__ float Ks[32][68];
    __shared__ float Vs[32][68];

    const int t  = threadIdx.x;
    const int tx = t & 15;
    const int ty = t >> 4;
    const int b  = blockIdx.y;
    const int s0 = blockIdx.x * CS;

    const float4* K4 = (const float4*)(g_K + ((size_t)b * TT + s0) * HH);
    const float4* V4 = (const float4*)(g_V + ((size_t)b * TT + s0) * HH);

    float acc[4][4];
#pragma unroll
    for (int i = 0; i < 4; i++)
#pragma unroll
        for (int j = 0; j < 4; j++) acc[i][j] = 0.f;

#pragma unroll
    for (int l = 0; l < 2; l++) {
        int f   = t + l * 256;
        int row = f >> 4;
        int c4  = f & 15;
        float4 kv = K4[(size_t)row * 16 + c4];
        float4 vv = V4[(size_t)row * 16 + c4];
        *(float4*)&Ks[row][c4 * 4] = kv;
        *(float4*)&Vs[row][c4 * 4] = vv;
    }
    __syncthreads();

#pragma unroll 8
    for (int s = 0; s < 32; s++) {
        float4 a4 = *(const float4*)&Ks[s][ty * 4];
        float4 b4 = *(const float4*)&Vs[s][tx * 4];
        float a[4] = {a4.x, a4.y, a4.z, a4.w};
        float bb2[4] = {b4.x, b4.y, b4.z, b4.w};
#pragma unroll
        for (int i = 0; i < 4; i++)
#pragma unroll
            for (int j = 0; j < 4; j++)
                acc[i][j] += a[i] * bb2[j];
    }

    float* Mb = g_M + (size_t)b * HH * HH;
#pragma unroll
    for (int i = 0; i < 4; i++)
#pragma unroll
        for (int j = 0; j < 4; j++)
            atomicAdd(&Mb[(ty * 4 + i) * HH + tx * 4 + j], acc[i][j]);
}

// ---------------------------------------------------------------------------
// out[b] = SCALE * Q[b] @ M[b]
// ---------------------------------------------------------------------------
__global__ __launch_bounds__(256) void out_kernel(float* __restrict__ out)
{
    __shared__ float Ms[64][68];
    __shared__ float Qs[64][68];

    const int t    = threadIdx.x;
    const int tx   = t & 15;
    const int ty   = t >> 4;
    const int row0 = blockIdx.x * 64;
    const int b    = row0 / TT;

    const float4* Q4 = (const float4*)(g_Q + (size_t)row0 * HH);
    const float4* M4 = (const float4*)(g_M + (size_t)b * HH * HH);

#pragma unroll
    for (int l = 0; l < 4; l++) {
        int f   = t + l * 256;
        int row = f >> 4;
        int c4  = f & 15;
        float4 qv = Q4[(size_t)row * 16 + c4];
        float4 mv = M4[(size_t)row * 16 + c4];
        *(float4*)&Qs[row][c4 * 4] = qv;
        *(float4*)&Ms[row][c4 * 4] = mv;
    }
    __syncthreads();

    float acc[4][4];
#pragma unroll
    for (int i = 0; i < 4; i++)
#pragma unroll
        for (int j = 0; j < 4; j++) acc[i][j] = 0.f;

#pragma unroll 4
    for (int k0 = 0; k0 < 64; k0 += 4) {
        float4 q4[4];
#pragma unroll
        for (int i = 0; i < 4; i++)
            q4[i] = *(const float4*)&Qs[ty * 4 + i][k0];
#pragma unroll
        for (int kk = 0; kk < 4; kk++) {
            float4 m4 = *(const float4*)&Ms[k0 + kk][tx * 4];
            float m[4] = {m4.x, m4.y, m4.z, m4.w};
#pragma unroll
            for (int i = 0; i < 4; i++) {
                float qv = (kk == 0) ? q4[i].x : (kk == 1) ? q4[i].y
                         : (kk == 2) ? q4[i].z : q4[i].w;
#pragma unroll
                for (int j = 0; j < 4; j++)
                    acc[i][j] += qv * m[j];
            }
        }
    }

#pragma unroll
    for (int i = 0; i < 4; i++) {
        int r = row0 + ty * 4 + i;
        float4 o;
        o.x = acc[i][0] * SCALE;
        o.y = acc[i][1] * SCALE;
        o.z = acc[i][2] * SCALE;
        o.w = acc[i][3] * SCALE;
        *(float4*)&out[(size_t)r * HH + tx * 4] = o;
    }
}

// ---------------------------------------------------------------------------
// Launch
// ---------------------------------------------------------------------------
extern "C" void kernel_launch(void* const* d_in, const int* in_sizes, int n_in,
                              void* d_out, int out_size)
{
    const float* idx = (const float*)d_in[0];
    const float* Wq  = (const float*)d_in[1];
    const float* bq  = (const float*)d_in[2];
    const float* Wk  = (const float*)d_in[3];
    const float* bk  = (const float*)d_in[4];
    const float* Wv  = (const float*)d_in[5];
    const float* bv  = (const float*)d_in[6];
    float* out = (float*)d_out;

    static bool attr_set = false;
    if (!attr_set) {
        cudaFuncSetAttribute(qkv_mma_kernel,
                             cudaFuncAttributeMaxDynamicSharedMemorySize, QKV_SMEM);
        attr_set = true;
    }

    prep_kernel<<<(192 * EE + 255) / 256, 256>>>(Wq, Wk, Wv);

    qkv_mma_kernel<<<dim3(BT / 128, 3), 256, QKV_SMEM>>>(idx, bq, bk, bv);

    kv_outer_kernel<<<dim3(TT / CS, BB), 256>>>();

    out_kernel<<<BT / 64, 256>>>(out);
}

// round 8
// speedup vs baseline: 2.4504x; 1.2905x over previous
#include <cuda_runtime.h>
#include <cuda_fp16.h>
#include <cstdint>

// Problem dims (fixed)
#define BB 4
#define TT 4096
#define EE 1024
#define HH 64
#define BT (BB * TT)          // 16384 rows
#define SCALE 0.03125f        // E^-0.5

// Scratch (device globals)
__device__ float g_Q[BT * HH];
__device__ float g_K[BT * HH];
__device__ float g_V[BT * HH];
__device__ float g_M[BB * HH * HH];
__device__ __half g_WT_hi[192 * EE];   // [n][k]; n: q 0-63, k 64-127, v 128-191
__device__ __half g_WT_lo[192 * EE];

// ---------------------------------------------------------------------------
// PTX helpers (baseline PTX, valid under compute_103)
// ---------------------------------------------------------------------------
#define MMA_FP16(c, a, b)                                                     \
    asm volatile(                                                             \
        "mma.sync.aligned.m16n8k16.row.col.f32.f16.f16.f32 "                  \
        "{%0,%1,%2,%3}, {%4,%5,%6,%7}, {%8,%9}, {%0,%1,%2,%3};\n"             \
        : "+f"(c[0]), "+f"(c[1]), "+f"(c[2]), "+f"(c[3])                      \
        : "r"(a[0]), "r"(a[1]), "r"(a[2]), "r"(a[3]), "r"(b[0]), "r"(b[1]))

#define LDSM4(r0, r1, r2, r3, addr)                                           \
    asm volatile("ldmatrix.sync.aligned.m8n8.x4.shared.b16 {%0,%1,%2,%3}, [%4];" \
        : "=r"(r0), "=r"(r1), "=r"(r2), "=r"(r3) : "r"(addr))

#define CP_ASYNC16(dst, src) \
    asm volatile("cp.async.cg.shared.global [%0], [%1], 16;" :: "r"(dst), "l"(src))
#define CP_COMMIT() asm volatile("cp.async.commit_group;")
#define CP_WAIT0()  asm volatile("cp.async.wait_group 0;")

__device__ __forceinline__ uint32_t smem_u32(const void* p) {
    uint32_t a;
    asm("{ .reg .u64 t; cvta.to.shared.u64 t, %1; cvt.u32.u64 %0, t; }" : "=r"(a) : "l"(p));
    return a;
}

// ---------------------------------------------------------------------------
// Prep: zero g_M + split Wq|Wk|Wv (fp32 [k][n]) -> fp16 hi/lo transposed [n][k]
// ---------------------------------------------------------------------------
__global__ void prep_kernel(const float* __restrict__ Wq,
                            const float* __restrict__ Wk,
                            const float* __restrict__ Wv)
{
    int i = blockIdx.x * blockDim.x + threadIdx.x;
    if (i < BB * HH * HH) g_M[i] = 0.f;
    if (i >= 192 * EE) return;
    int n = i % 192;
    int k = i / 192;
    const float* W = (n < 64) ? Wq : ((n < 128) ? Wk : Wv);
    float v = W[k * HH + (n & 63)];
    __half hi = __float2half_rn(v);
    __half lo = __float2half_rn(v - __half2float(hi));
    g_WT_hi[(size_t)n * EE + k] = hi;
    g_WT_lo[(size_t)n * EE + k] = lo;
}

// ---------------------------------------------------------------------------
// QKV projection: fp16 2-pass (X single fp16; W = hi+lo fp16 planes).
// grid = (BT/128, 3), 256 threads = 8 warps (4M x 2N), warp tile 32x32, BK=32.
//
// Dynamic smem per buffer (stride 20480B):
//   Xh [128][40]f16 @ 0      (10240)
//   Wh [ 64][40]    @ 10240  ( 5120)
//   Wl [ 64][40]    @ 15360  ( 5120)
// Two buffers = 40960 B.
// ---------------------------------------------------------------------------
#define BUFS 20480
#define QKV_SMEM (2 * BUFS)

__global__ __launch_bounds__(256) void qkv_mma_kernel(
    const float* __restrict__ X,
    const float* __restrict__ bq,
    const float* __restrict__ bkk,
    const float* __restrict__ bv)
{
    extern __shared__ __align__(16) char sm[];
    const uint32_t sb = smem_u32(sm);
    const int t    = threadIdx.x;
    const int warp = t >> 5;
    const int lane = t & 31;
    const int g    = lane >> 2;
    const int tig  = lane & 3;
    const int wm   = warp >> 1;      // 0..3 -> m offset 32*wm
    const int wn   = warp & 1;       // 0..1 -> n offset 32*wn
    const int m0   = blockIdx.x * 128;
    const int which = blockIdx.y;

    const float4* X4 = (const float4*)X;
    const __half* WHp = g_WT_hi + (size_t)which * 64 * EE;
    const __half* WLp = g_WT_lo + (size_t)which * 64 * EE;

    float c[2][4][4];
#pragma unroll
    for (int mt = 0; mt < 2; mt++)
#pragma unroll
        for (int nt = 0; nt < 4; nt++)
#pragma unroll
            for (int j = 0; j < 4; j++) c[mt][nt][j] = 0.f;

    float4 xr[4];
    const int xrow = t >> 3;         // 0..31 (4 rows per thread, stride 32)
    const int xc4  = t & 7;          // float4 chunk within 32-col tile

    // prefetch X tile (k0) into registers
    auto ldgX = [&](int k0) {
#pragma unroll
        for (int j = 0; j < 4; j++)
            xr[j] = X4[(size_t)(m0 + xrow + j * 32) * (EE / 4) + (k0 >> 2) + xc4];
    };
    // convert + store X registers -> buffer (single fp16 plane)
    auto stX = [&](int buf) {
        char* xh = sm + buf * BUFS;
#pragma unroll
        for (int j = 0; j < 4; j++) {
            __half2 p0 = __floats2half2_rn(xr[j].x, xr[j].y);
            __half2 p1 = __floats2half2_rn(xr[j].z, xr[j].w);
            int off = (xrow + j * 32) * 80 + xc4 * 8;
            *(uint2*)(xh + off) = make_uint2(*(uint32_t*)&p0, *(uint32_t*)&p1);
        }
    };
    // async-copy W tile (k0) -> buffer (hi+lo planes, 512 x 16B, 2 per thread)
    auto cpW = [&](int k0, int buf) {
        uint32_t wbase = sb + buf * BUFS + 10240;
#pragma unroll
        for (int j = 0; j < 2; j++) {
            int cc = t + j * 256;          // 0..511
            int plane = cc >> 8;           // 0 hi, 1 lo
            int c2 = cc & 255;
            int row = c2 >> 2;             // 0..63
            int q = c2 & 3;                // 16B chunk within 64B row
            const __half* src = (plane ? WLp : WHp) + (size_t)row * EE + k0 + q * 8;
            uint32_t dst = wbase + plane * 5120 + row * 80 + q * 16;
            CP_ASYNC16(dst, src);
        }
    };
    // 2 ks-steps of 16: ldmatrix fragments + 32 MMAs (2 passes)
    auto domma = [&](int buf) {
        uint32_t xh = sb + buf * BUFS;
#pragma unroll
        for (int ks = 0; ks < 2; ks++) {
            const int kboff = ks * 32;     // bytes
            uint32_t a[2][4], bh[4][2], bl[4][2];
#pragma unroll
            for (int mt = 0; mt < 2; mt++) {
                uint32_t addr = xh + (uint32_t)((wm * 32 + mt * 16 + (lane & 15)) * 80
                                                + kboff + (lane >> 4) * 16);
                LDSM4(a[mt][0], a[mt][1], a[mt][2], a[mt][3], addr);
            }
#pragma unroll
            for (int nb = 0; nb < 2; nb++) {
                uint32_t addr = xh + 10240 + (uint32_t)((wn * 32 + nb * 16 + (lane & 15)) * 80
                                                        + kboff + (lane >> 4) * 16);
                uint32_t r0, r1, r2, r3;
                LDSM4(r0, r1, r2, r3, addr);
                bh[nb * 2][0] = r0; bh[nb * 2][1] = r2;
                bh[nb * 2 + 1][0] = r1; bh[nb * 2 + 1][1] = r3;
                LDSM4(r0, r1, r2, r3, addr + 5120);
                bl[nb * 2][0] = r0; bl[nb * 2][1] = r2;
                bl[nb * 2 + 1][0] = r1; bl[nb * 2 + 1][1] = r3;
            }
#pragma unroll
            for (int mt = 0; mt < 2; mt++)
#pragma unroll
                for (int nt = 0; nt < 4; nt++) {
                    MMA_FP16(c[mt][nt], a[mt], bh[nt]);   // x * w_hi
                    MMA_FP16(c[mt][nt], a[mt], bl[nt]);   // x * w_lo
                }
        }
    };

    // ---- pipelined mainloop: 32 tiles of BK=32 ----
    ldgX(0);
    cpW(0, 0);
    CP_COMMIT();
    stX(0);
    for (int i = 0; i < 32; i++) {
        int buf = i & 1;
        CP_WAIT0();
        __syncthreads();
        if (i < 31) {
            ldgX((i + 1) * 32);
            cpW((i + 1) * 32, buf ^ 1);
            CP_COMMIT();
        }
        domma(buf);
        if (i < 31) stX(buf ^ 1);
    }

    // ---- epilogue: bias + store fp32 ----
    const float* bias = (which == 0) ? bq : (which == 1) ? bkk : bv;
    float* __restrict__ outp = (which == 0) ? g_Q : (which == 1) ? g_K : g_V;
#pragma unroll
    for (int mt = 0; mt < 2; mt++) {
        int r0 = m0 + wm * 32 + mt * 16 + g;
#pragma unroll
        for (int nt = 0; nt < 4; nt++) {
            int n = wn * 32 + nt * 8 + 2 * tig;
            float b0v = bias[n];
            float b1v = bias[n + 1];
            float2 o0 = {c[mt][nt][0] + b0v, c[mt][nt][1] + b1v};
            float2 o1 = {c[mt][nt][2] + b0v, c[mt][nt][3] + b1v};
            *(float2*)&outp[(size_t)r0 * HH + n] = o0;
            *(float2*)&outp[(size_t)(r0 + 8) * HH + n] = o1;
        }
    }
}

// ---------------------------------------------------------------------------
// M[b] += K[b]^T @ V[b]; CS=32 -> grid (128, 4) = 512 blocks.
// ---------------------------------------------------------------------------
#define CS 32
__global__ __launch_bounds__(256) void kv_outer_kernel()
{
    __shared__ float Ks[32][68];
    __shared__ float Vs[32][68];

    const int t  = threadIdx.x;
    const int tx = t & 15;
    const int ty = t >> 4;
    const int b  = blockIdx.y;
    const int s0 = blockIdx.x * CS;

    const float4* K4 = (const float4*)(g_K + ((size_t)b * TT + s0) * HH);
    const float4* V4 = (const float4*)(g_V + ((size_t)b * TT + s0) * HH);

    float acc[4][4];
#pragma unroll
    for (int i = 0; i < 4; i++)
#pragma unroll
        for (int j = 0; j < 4; j++) acc[i][j] = 0.f;

#pragma unroll
    for (int l = 0; l < 2; l++) {
        int f   = t + l * 256;
        int row = f >> 4;
        int c4  = f & 15;
        float4 kv = K4[(size_t)row * 16 + c4];
        float4 vv = V4[(size_t)row * 16 + c4];
        *(float4*)&Ks[row][c4 * 4] = kv;
        *(float4*)&Vs[row][c4 * 4] = vv;
    }
    __syncthreads();

#pragma unroll 8
    for (int s = 0; s < 32; s++) {
        float4 a4 = *(const float4*)&Ks[s][ty * 4];
        float4 b4 = *(const float4*)&Vs[s][tx * 4];
        float a[4] = {a4.x, a4.y, a4.z, a4.w};
        float bb2[4] = {b4.x, b4.y, b4.z, b4.w};
#pragma unroll
        for (int i = 0; i < 4; i++)
#pragma unroll
            for (int j = 0; j < 4; j++)
                acc[i][j] += a[i] * bb2[j];
    }

    float* Mb = g_M + (size_t)b * HH * HH;
#pragma unroll
    for (int i = 0; i < 4; i++)
#pragma unroll
        for (int j = 0; j < 4; j++)
            atomicAdd(&Mb[(ty * 4 + i) * HH + tx * 4 + j], acc[i][j]);
}

// ---------------------------------------------------------------------------
// out[b] = SCALE * Q[b] @ M[b]
// ---------------------------------------------------------------------------
__global__ __launch_bounds__(256) void out_kernel(float* __restrict__ out)
{
    __shared__ float Ms[64][68];
    __shared__ float Qs[64][68];

    const int t    = threadIdx.x;
    const int tx   = t & 15;
    const int ty   = t >> 4;
    const int row0 = blockIdx.x * 64;
    const int b    = row0 / TT;

    const float4* Q4 = (const float4*)(g_Q + (size_t)row0 * HH);
    const float4* M4 = (const float4*)(g_M + (size_t)b * HH * HH);

#pragma unroll
    for (int l = 0; l < 4; l++) {
        int f   = t + l * 256;
        int row = f >> 4;
        int c4  = f & 15;
        float4 qv = Q4[(size_t)row * 16 + c4];
        float4 mv = M4[(size_t)row * 16 + c4];
        *(float4*)&Qs[row][c4 * 4] = qv;
        *(float4*)&Ms[row][c4 * 4] = mv;
    }
    __syncthreads();

    float acc[4][4];
#pragma unroll
    for (int i = 0; i < 4; i++)
#pragma unroll
        for (int j = 0; j < 4; j++) acc[i][j] = 0.f;

#pragma unroll 4
    for (int k0 = 0; k0 < 64; k0 += 4) {
        float4 q4[4];
#pragma unroll
        for (int i = 0; i < 4; i++)
            q4[i] = *(const float4*)&Qs[ty * 4 + i][k0];
#pragma unroll
        for (int kk = 0; kk < 4; kk++) {
            float4 m4 = *(const float4*)&Ms[k0 + kk][tx * 4];
            float m[4] = {m4.x, m4.y, m4.z, m4.w};
#pragma unroll
            for (int i = 0; i < 4; i++) {
                float qv = (kk == 0) ? q4[i].x : (kk == 1) ? q4[i].y
                         : (kk == 2) ? q4[i].z : q4[i].w;
#pragma unroll
                for (int j = 0; j < 4; j++)
                    acc[i][j] += qv * m[j];
            }
        }
    }

#pragma unroll
    for (int i = 0; i < 4; i++) {
        int r = row0 + ty * 4 + i;
        float4 o;
        o.x = acc[i][0] * SCALE;
        o.y = acc[i][1] * SCALE;
        o.z = acc[i][2] * SCALE;
        o.w = acc[i][3] * SCALE;
        *(float4*)&out[(size_t)r * HH + tx * 4] = o;
    }
}

// ---------------------------------------------------------------------------
// Launch
// ---------------------------------------------------------------------------
extern "C" void kernel_launch(void* const* d_in, const int* in_sizes, int n_in,
                              void* d_out, int out_size)
{
    const float* idx = (const float*)d_in[0];
    const float* Wq  = (const float*)d_in[1];
    const float* bq  = (const float*)d_in[2];
    const float* Wk  = (const float*)d_in[3];
    const float* bk  = (const float*)d_in[4];
    const float* Wv  = (const float*)d_in[5];
    const float* bv  = (const float*)d_in[6];
    float* out = (float*)d_out;

    static bool attr_set = false;
    if (!attr_set) {
        cudaFuncSetAttribute(qkv_mma_kernel,
                             cudaFuncAttributeMaxDynamicSharedMemorySize, QKV_SMEM);
        attr_set = true;
    }

    prep_kernel<<<(192 * EE + 255) / 256, 256>>>(Wq, Wk, Wv);

    qkv_mma_kernel<<<dim3(BT / 128, 3), 256, QKV_SMEM>>>(idx, bq, bk, bv);

    kv_outer_kernel<<<dim3(TT / CS, BB), 256>>>();

    out_kernel<<<BT / 64, 256>>>(out);
}

// round 9
// speedup vs baseline: 3.1236x; 1.2747x over previous
#include <cuda_runtime.h>
#include <cuda_fp16.h>
#include <cstdint>

// Problem dims (fixed)
#define BB 4
#define TT 4096
#define EE 1024
#define HH 64
#define BT (BB * TT)          // 16384 rows
#define SCALE 0.03125f        // E^-0.5

// Scratch (device globals)
__device__ float g_Q[BT * HH];
__device__ float g_K[BT * HH];
__device__ float g_V[BT * HH];
__device__ float g_M[BB * HH * HH];
__device__ __half g_WT[192 * EE];   // [n][k]; n: q 0-63, k 64-127, v 128-191

// ---------------------------------------------------------------------------
// PTX helpers (baseline PTX, valid under compute_103)
// ---------------------------------------------------------------------------
#define MMA_FP16(c, a, b)                                                     \
    asm volatile(                                                             \
        "mma.sync.aligned.m16n8k16.row.col.f32.f16.f16.f32 "                  \
        "{%0,%1,%2,%3}, {%4,%5,%6,%7}, {%8,%9}, {%0,%1,%2,%3};\n"             \
        : "+f"(c[0]), "+f"(c[1]), "+f"(c[2]), "+f"(c[3])                      \
        : "r"(a[0]), "r"(a[1]), "r"(a[2]), "r"(a[3]), "r"(b[0]), "r"(b[1]))

#define LDSM4(r0, r1, r2, r3, addr)                                           \
    asm volatile("ldmatrix.sync.aligned.m8n8.x4.shared.b16 {%0,%1,%2,%3}, [%4];" \
        : "=r"(r0), "=r"(r1), "=r"(r2), "=r"(r3) : "r"(addr))

#define CP_ASYNC16(dst, src) \
    asm volatile("cp.async.cg.shared.global [%0], [%1], 16;" :: "r"(dst), "l"(src))
#define CP_COMMIT() asm volatile("cp.async.commit_group;")
#define CP_WAIT0()  asm volatile("cp.async.wait_group 0;")

__device__ __forceinline__ uint32_t smem_u32(const void* p) {
    uint32_t a;
    asm("{ .reg .u64 t; cvta.to.shared.u64 t, %1; cvt.u32.u64 %0, t; }" : "=r"(a) : "l"(p));
    return a;
}

// ---------------------------------------------------------------------------
// Prep: zero g_M + convert Wq|Wk|Wv (fp32 [k][n]) -> fp16 transposed [n][k]
// ---------------------------------------------------------------------------
__global__ void prep_kernel(const float* __restrict__ Wq,
                            const float* __restrict__ Wk,
                            const float* __restrict__ Wv)
{
    int i = blockIdx.x * blockDim.x + threadIdx.x;
    if (i < BB * HH * HH) g_M[i] = 0.f;
    if (i >= 192 * EE) return;
    int n = i % 192;
    int k = i / 192;
    const float* W = (n < 64) ? Wq : ((n < 128) ? Wk : Wv);
    g_WT[(size_t)n * EE + k] = __float2half_rn(W[k * HH + (n & 63)]);
}

// ---------------------------------------------------------------------------
// QKV projection: single fp16 pass (X fp16, W fp16).
// grid = (BT/128, 3), 256 threads = 8 warps (4M x 2N), warp tile 32x32, BK=32.
//
// Dynamic smem per buffer (stride 15360B):
//   Xh [128][40]f16 @ 0      (10240)
//   Wh [ 64][40]    @ 10240  ( 5120)
// Two buffers = 30720 B.
// ---------------------------------------------------------------------------
#define BUFS 15360
#define QKV_SMEM (2 * BUFS)

__global__ __launch_bounds__(256) void qkv_mma_kernel(
    const float* __restrict__ X,
    const float* __restrict__ bq,
    const float* __restrict__ bkk,
    const float* __restrict__ bv)
{
    extern __shared__ __align__(16) char sm[];
    const uint32_t sb = smem_u32(sm);
    const int t    = threadIdx.x;
    const int warp = t >> 5;
    const int lane = t & 31;
    const int g    = lane >> 2;
    const int tig  = lane & 3;
    const int wm   = warp >> 1;      // 0..3 -> m offset 32*wm
    const int wn   = warp & 1;       // 0..1 -> n offset 32*wn
    const int m0   = blockIdx.x * 128;
    const int which = blockIdx.y;

    const float4* X4 = (const float4*)X;
    const __half* WHp = g_WT + (size_t)which * 64 * EE;

    float c[2][4][4];
#pragma unroll
    for (int mt = 0; mt < 2; mt++)
#pragma unroll
        for (int nt = 0; nt < 4; nt++)
#pragma unroll
            for (int j = 0; j < 4; j++) c[mt][nt][j] = 0.f;

    float4 xr[4];
    const int xrow = t >> 3;         // 0..31 (4 rows per thread, stride 32)
    const int xc4  = t & 7;          // float4 chunk within 32-col tile

    // prefetch X tile (k0) into registers
    auto ldgX = [&](int k0) {
#pragma unroll
        for (int j = 0; j < 4; j++)
            xr[j] = X4[(size_t)(m0 + xrow + j * 32) * (EE / 4) + (k0 >> 2) + xc4];
    };
    // convert + store X registers -> buffer (fp16)
    auto stX = [&](int buf) {
        char* xh = sm + buf * BUFS;
#pragma unroll
        for (int j = 0; j < 4; j++) {
            __half2 p0 = __floats2half2_rn(xr[j].x, xr[j].y);
            __half2 p1 = __floats2half2_rn(xr[j].z, xr[j].w);
            int off = (xrow + j * 32) * 80 + xc4 * 8;
            *(uint2*)(xh + off) = make_uint2(*(uint32_t*)&p0, *(uint32_t*)&p1);
        }
    };
    // async-copy W tile (k0) -> buffer (256 x 16B, 1 per thread)
    auto cpW = [&](int k0, int buf) {
        uint32_t wbase = sb + buf * BUFS + 10240;
        int row = t >> 2;              // 0..63
        int q = t & 3;                 // 16B chunk within 64B row
        const __half* src = WHp + (size_t)row * EE + k0 + q * 8;
        uint32_t dst = wbase + row * 80 + q * 16;
        CP_ASYNC16(dst, src);
    };
    // 2 ks-steps of 16: ldmatrix fragments + 16 MMAs
    auto domma = [&](int buf) {
        uint32_t xh = sb + buf * BUFS;
#pragma unroll
        for (int ks = 0; ks < 2; ks++) {
            const int kboff = ks * 32;     // bytes
            uint32_t a[2][4], bh[4][2];
#pragma unroll
            for (int mt = 0; mt < 2; mt++) {
                uint32_t addr = xh + (uint32_t)((wm * 32 + mt * 16 + (lane & 15)) * 80
                                                + kboff + (lane >> 4) * 16);
                LDSM4(a[mt][0], a[mt][1], a[mt][2], a[mt][3], addr);
            }
#pragma unroll
            for (int nb = 0; nb < 2; nb++) {
                uint32_t addr = xh + 10240 + (uint32_t)((wn * 32 + nb * 16 + (lane & 15)) * 80
                                                        + kboff + (lane >> 4) * 16);
                uint32_t r0, r1, r2, r3;
                LDSM4(r0, r1, r2, r3, addr);
                bh[nb * 2][0] = r0; bh[nb * 2][1] = r2;
                bh[nb * 2 + 1][0] = r1; bh[nb * 2 + 1][1] = r3;
            }
#pragma unroll
            for (int mt = 0; mt < 2; mt++)
#pragma unroll
                for (int nt = 0; nt < 4; nt++)
                    MMA_FP16(c[mt][nt], a[mt], bh[nt]);
        }
    };

    // ---- pipelined mainloop: 32 tiles of BK=32 ----
    ldgX(0);
    cpW(0, 0);
    CP_COMMIT();
    stX(0);
    for (int i = 0; i < 32; i++) {
        int buf = i & 1;
        CP_WAIT0();
        __syncthreads();
        if (i < 31) {
            ldgX((i + 1) * 32);
            cpW((i + 1) * 32, buf ^ 1);
            CP_COMMIT();
        }
        domma(buf);
        if (i < 31) stX(buf ^ 1);
    }

    // ---- epilogue: bias + store fp32 ----
    const float* bias = (which == 0) ? bq : (which == 1) ? bkk : bv;
    float* __restrict__ outp = (which == 0) ? g_Q : (which == 1) ? g_K : g_V;
#pragma unroll
    for (int mt = 0; mt < 2; mt++) {
        int r0 = m0 + wm * 32 + mt * 16 + g;
#pragma unroll
        for (int nt = 0; nt < 4; nt++) {
            int n = wn * 32 + nt * 8 + 2 * tig;
            float b0v = bias[n];
            float b1v = bias[n + 1];
            float2 o0 = {c[mt][nt][0] + b0v, c[mt][nt][1] + b1v};
            float2 o1 = {c[mt][nt][2] + b0v, c[mt][nt][3] + b1v};
            *(float2*)&outp[(size_t)r0 * HH + n] = o0;
            *(float2*)&outp[(size_t)(r0 + 8) * HH + n] = o1;
        }
    }
}

// ---------------------------------------------------------------------------
// M[b] += K[b]^T @ V[b]; CS=32 -> grid (128, 4) = 512 blocks.
// ---------------------------------------------------------------------------
#define CS 32
__global__ __launch_bounds__(256) void kv_outer_kernel()
{
    __shared__ float Ks[32][68];
    __shared__ float Vs[32][68];

    const int t  = threadIdx.x;
    const int tx = t & 15;
    const int ty = t >> 4;
    const int b  = blockIdx.y;
    const int s0 = blockIdx.x * CS;

    const float4* K4 = (const float4*)(g_K + ((size_t)b * TT + s0) * HH);
    const float4* V4 = (const float4*)(g_V + ((size_t)b * TT + s0) * HH);

    float acc[4][4];
#pragma unroll
    for (int i = 0; i < 4; i++)
#pragma unroll
        for (int j = 0; j < 4; j++) acc[i][j] = 0.f;

#pragma unroll
    for (int l = 0; l < 2; l++) {
        int f   = t + l * 256;
        int row = f >> 4;
        int c4  = f & 15;
        float4 kv = K4[(size_t)row * 16 + c4];
        float4 vv = V4[(size_t)row * 16 + c4];
        *(float4*)&Ks[row][c4 * 4] = kv;
        *(float4*)&Vs[row][c4 * 4] = vv;
    }
    __syncthreads();

#pragma unroll 8
    for (int s = 0; s < 32; s++) {
        float4 a4 = *(const float4*)&Ks[s][ty * 4];
        float4 b4 = *(const float4*)&Vs[s][tx * 4];
        float a[4] = {a4.x, a4.y, a4.z, a4.w};
        float bb2[4] = {b4.x, b4.y, b4.z, b4.w};
#pragma unroll
        for (int i = 0; i < 4; i++)
#pragma unroll
            for (int j = 0; j < 4; j++)
                acc[i][j] += a[i] * bb2[j];
    }

    float* Mb = g_M + (size_t)b * HH * HH;
#pragma unroll
    for (int i = 0; i < 4; i++)
#pragma unroll
        for (int j = 0; j < 4; j++)
            atomicAdd(&Mb[(ty * 4 + i) * HH + tx * 4 + j], acc[i][j]);
}

// ---------------------------------------------------------------------------
// out[b] = SCALE * Q[b] @ M[b]
// ---------------------------------------------------------------------------
__global__ __launch_bounds__(256) void out_kernel(float* __restrict__ out)
{
    __shared__ float Ms[64][68];
    __shared__ float Qs[64][68];

    const int t    = threadIdx.x;
    const int tx   = t & 15;
    const int ty   = t >> 4;
    const int row0 = blockIdx.x * 64;
    const int b    = row0 / TT;

    const float4* Q4 = (const float4*)(g_Q + (size_t)row0 * HH);
    const float4* M4 = (const float4*)(g_M + (size_t)b * HH * HH);

#pragma unroll
    for (int l = 0; l < 4; l++) {
        int f   = t + l * 256;
        int row = f >> 4;
        int c4  = f & 15;
        float4 qv = Q4[(size_t)row * 16 + c4];
        float4 mv = M4[(size_t)row * 16 + c4];
        *(float4*)&Qs[row][c4 * 4] = qv;
        *(float4*)&Ms[row][c4 * 4] = mv;
    }
    __syncthreads();

    float acc[4][4];
#pragma unroll
    for (int i = 0; i < 4; i++)
#pragma unroll
        for (int j = 0; j < 4; j++) acc[i][j] = 0.f;

#pragma unroll 4
    for (int k0 = 0; k0 < 64; k0 += 4) {
        float4 q4[4];
#pragma unroll
        for (int i = 0; i < 4; i++)
            q4[i] = *(const float4*)&Qs[ty * 4 + i][k0];
#pragma unroll
        for (int kk = 0; kk < 4; kk++) {
            float4 m4 = *(const float4*)&Ms[k0 + kk][tx * 4];
            float m[4] = {m4.x, m4.y, m4.z, m4.w};
#pragma unroll
            for (int i = 0; i < 4; i++) {
                float qv = (kk == 0) ? q4[i].x : (kk == 1) ? q4[i].y
                         : (kk == 2) ? q4[i].z : q4[i].w;
#pragma unroll
                for (int j = 0; j < 4; j++)
                    acc[i][j] += qv * m[j];
            }
        }
    }

#pragma unroll
    for (int i = 0; i < 4; i++) {
        int r = row0 + ty * 4 + i;
        float4 o;
        o.x = acc[i][0] * SCALE;
        o.y = acc[i][1] * SCALE;
        o.z = acc[i][2] * SCALE;
        o.w = acc[i][3] * SCALE;
        *(float4*)&out[(size_t)r * HH + tx * 4] = o;
    }
}

// ---------------------------------------------------------------------------
// Launch
// ---------------------------------------------------------------------------
extern "C" void kernel_launch(void* const* d_in, const int* in_sizes, int n_in,
                              void* d_out, int out_size)
{
    const float* idx = (const float*)d_in[0];
    const float* Wq  = (const float*)d_in[1];
    const float* bq  = (const float*)d_in[2];
    const float* Wk  = (const float*)d_in[3];
    const float* bk  = (const float*)d_in[4];
    const float* Wv  = (const float*)d_in[5];
    const float* bv  = (const float*)d_in[6];
    float* out = (float*)d_out;

    static bool attr_set = false;
    if (!attr_set) {
        cudaFuncSetAttribute(qkv_mma_kernel,
                             cudaFuncAttributeMaxDynamicSharedMemorySize, QKV_SMEM);
        attr_set = true;
    }

    prep_kernel<<<(192 * EE + 255) / 256, 256>>>(Wq, Wk, Wv);

    qkv_mma_kernel<<<dim3(BT / 128, 3), 256, QKV_SMEM>>>(idx, bq, bk, bv);

    kv_outer_kernel<<<dim3(TT / CS, BB), 256>>>();

    out_kernel<<<BT / 64, 256>>>(out);
}

// round 10
// speedup vs baseline: 3.2573x; 1.0428x over previous
#include <cuda_runtime.h>
#include <cuda_fp16.h>
#include <cstdint>

// Problem dims (fixed)
#define BB 4
#define TT 4096
#define EE 1024
#define HH 64
#define BT (BB * TT)          // 16384 rows
#define SCALE 0.03125f        // E^-0.5

// Scratch (device globals)
__device__ float g_Q[BT * HH];
__device__ float g_K[BT * HH];
__device__ float g_V[BT * HH];
__device__ float g_M[BB * HH * HH];
__device__ __half g_WT[192 * EE];   // [n][k]; n: q 0-63, k 64-127, v 128-191

// ---------------------------------------------------------------------------
// PTX helpers (baseline PTX, valid under compute_103)
// ---------------------------------------------------------------------------
#define MMA_FP16(c, a, b)                                                     \
    asm volatile(                                                             \
        "mma.sync.aligned.m16n8k16.row.col.f32.f16.f16.f32 "                  \
        "{%0,%1,%2,%3}, {%4,%5,%6,%7}, {%8,%9}, {%0,%1,%2,%3};\n"             \
        : "+f"(c[0]), "+f"(c[1]), "+f"(c[2]), "+f"(c[3])                      \
        : "r"(a[0]), "r"(a[1]), "r"(a[2]), "r"(a[3]), "r"(b[0]), "r"(b[1]))

#define LDSM4(r0, r1, r2, r3, addr)                                           \
    asm volatile("ldmatrix.sync.aligned.m8n8.x4.shared.b16 {%0,%1,%2,%3}, [%4];" \
        : "=r"(r0), "=r"(r1), "=r"(r2), "=r"(r3) : "r"(addr))

#define CP_ASYNC16(dst, src) \
    asm volatile("cp.async.cg.shared.global [%0], [%1], 16;" :: "r"(dst), "l"(src))
#define CP_COMMIT() asm volatile("cp.async.commit_group;")
#define CP_WAIT0()  asm volatile("cp.async.wait_group 0;")

__device__ __forceinline__ uint32_t smem_u32(const void* p) {
    uint32_t a;
    asm("{ .reg .u64 t; cvta.to.shared.u64 t, %1; cvt.u32.u64 %0, t; }" : "=r"(a) : "l"(p));
    return a;
}

// ---------------------------------------------------------------------------
// Prep: zero g_M + convert Wq|Wk|Wv (fp32 [k][n]) -> fp16 transposed [n][k]
// ---------------------------------------------------------------------------
__global__ void prep_kernel(const float* __restrict__ Wq,
                            const float* __restrict__ Wk,
                            const float* __restrict__ Wv)
{
    int i = blockIdx.x * blockDim.x + threadIdx.x;
    if (i < BB * HH * HH) g_M[i] = 0.f;
    if (i >= 192 * EE) return;
    int n = i % 192;
    int k = i / 192;
    const float* W = (n < 64) ? Wq : ((n < 128) ? Wk : Wv);
    g_WT[(size_t)n * EE + k] = __float2half_rn(W[k * HH + (n & 63)]);
}

// ---------------------------------------------------------------------------
// Fused QKV projection: single fp16 pass, one block = 64 rows x 192 cols.
// X loaded/converted ONCE per row (not 3x). grid = BT/64 = 256 blocks.
// 256 threads = 8 warps (2M x 4N), warp tile 32(M) x 48(N). BK=32.
//
// Dynamic smem per buffer (stride 20480B):
//   Xh [ 64][40]f16 @ 0      ( 5120)
//   Wh [192][40]    @ 5120   (15360)
// Two buffers = 40960 B  (2 blocks/SM co-resident)
// ---------------------------------------------------------------------------
#define BUFS 20480
#define QKV_SMEM (2 * BUFS)

__global__ __launch_bounds__(256) void qkv_mma_kernel(
    const float* __restrict__ X,
    const float* __restrict__ bq,
    const float* __restrict__ bkk,
    const float* __restrict__ bv)
{
    extern __shared__ __align__(16) char sm[];
    const uint32_t sb = smem_u32(sm);
    const int t    = threadIdx.x;
    const int warp = t >> 5;
    const int lane = t & 31;
    const int g    = lane >> 2;
    const int tig  = lane & 3;
    const int wm   = warp >> 2;      // 0..1 -> m offset 32*wm
    const int wn   = warp & 3;       // 0..3 -> n offset 48*wn
    const int m0   = blockIdx.x * 64;

    const float4* X4 = (const float4*)X;

    float c[2][6][4];
#pragma unroll
    for (int mt = 0; mt < 2; mt++)
#pragma unroll
        for (int nt = 0; nt < 6; nt++)
#pragma unroll
            for (int j = 0; j < 4; j++) c[mt][nt][j] = 0.f;

    float4 xr[2];
    const int xrow = t >> 2;         // 0..63 (1 row, 2 chunks per thread)
    const int xc4  = (t & 3) * 2;    // float4 chunks xc4, xc4+1

    // prefetch X tile (k0) into registers
    auto ldgX = [&](int k0) {
#pragma unroll
        for (int j = 0; j < 2; j++)
            xr[j] = X4[(size_t)(m0 + xrow) * (EE / 4) + (k0 >> 2) + xc4 + j];
    };
    // convert + store X registers -> buffer (fp16)
    auto stX = [&](int buf) {
        char* xh = sm + buf * BUFS;
#pragma unroll
        for (int j = 0; j < 2; j++) {
            __half2 p0 = __floats2half2_rn(xr[j].x, xr[j].y);
            __half2 p1 = __floats2half2_rn(xr[j].z, xr[j].w);
            int off = xrow * 80 + (xc4 + j) * 8;
            *(uint2*)(xh + off) = make_uint2(*(uint32_t*)&p0, *(uint32_t*)&p1);
        }
    };
    // async-copy W tile (k0): 192 rows x 32 cols fp16 = 768 x 16B, 3/thread
    auto cpW = [&](int k0, int buf) {
        uint32_t wbase = sb + buf * BUFS + 5120;
#pragma unroll
        for (int j = 0; j < 3; j++) {
            int cc = t + j * 256;          // 0..767
            int row = cc >> 2;             // 0..191
            int q = cc & 3;                // 16B chunk within 64B row
            const __half* src = g_WT + (size_t)row * EE + k0 + q * 8;
            uint32_t dst = wbase + row * 80 + q * 16;
            CP_ASYNC16(dst, src);
        }
    };
    // 2 ks-steps of 16: ldmatrix fragments + 24 MMAs
    auto domma = [&](int buf) {
        uint32_t xh = sb + buf * BUFS;
#pragma unroll
        for (int ks = 0; ks < 2; ks++) {
            const int kboff = ks * 32;     // bytes
            uint32_t a[2][4], bh[6][2];
#pragma unroll
            for (int mt = 0; mt < 2; mt++) {
                uint32_t addr = xh + (uint32_t)((wm * 32 + mt * 16 + (lane & 15)) * 80
                                                + kboff + (lane >> 4) * 16);
                LDSM4(a[mt][0], a[mt][1], a[mt][2], a[mt][3], addr);
            }
#pragma unroll
            for (int nb = 0; nb < 3; nb++) {
                uint32_t addr = xh + 5120 + (uint32_t)((wn * 48 + nb * 16 + (lane & 15)) * 80
                                                       + kboff + (lane >> 4) * 16);
                uint32_t r0, r1, r2, r3;
                LDSM4(r0, r1, r2, r3, addr);
                bh[nb * 2][0] = r0; bh[nb * 2][1] = r2;
                bh[nb * 2 + 1][0] = r1; bh[nb * 2 + 1][1] = r3;
            }
#pragma unroll
            for (int mt = 0; mt < 2; mt++)
#pragma unroll
                for (int nt = 0; nt < 6; nt++)
                    MMA_FP16(c[mt][nt], a[mt], bh[nt]);
        }
    };

    // ---- pipelined mainloop: 32 tiles of BK=32 ----
    ldgX(0);
    cpW(0, 0);
    CP_COMMIT();
    stX(0);
    for (int i = 0; i < 32; i++) {
        int buf = i & 1;
        CP_WAIT0();
        __syncthreads();
        if (i < 31) {
            ldgX((i + 1) * 32);
            cpW((i + 1) * 32, buf ^ 1);
            CP_COMMIT();
        }
        domma(buf);
        if (i < 31) stX(buf ^ 1);
    }

    // ---- epilogue: bias + store fp32, routed by column range ----
#pragma unroll
    for (int mt = 0; mt < 2; mt++) {
        int r0 = m0 + wm * 32 + mt * 16 + g;
#pragma unroll
        for (int nt = 0; nt < 6; nt++) {
            int nbase = wn * 48 + nt * 8;       // 8-aligned: never straddles 64
            int which = nbase >> 6;
            int nc    = (nbase & 63) + 2 * tig;
            const float* bias = (which == 0) ? bq : (which == 1) ? bkk : bv;
            float* __restrict__ outp = (which == 0) ? g_Q : (which == 1) ? g_K : g_V;
            float b0v = bias[nc];
            float b1v = bias[nc + 1];
            float2 o0 = {c[mt][nt][0] + b0v, c[mt][nt][1] + b1v};
            float2 o1 = {c[mt][nt][2] + b0v, c[mt][nt][3] + b1v};
            *(float2*)&outp[(size_t)r0 * HH + nc] = o0;
            *(float2*)&outp[(size_t)(r0 + 8) * HH + nc] = o1;
        }
    }
}

// ---------------------------------------------------------------------------
// M[b] += K[b]^T @ V[b]; CS=32 -> grid (128, 4) = 512 blocks.
// ---------------------------------------------------------------------------
#define CS 32
__global__ __launch_bounds__(256) void kv_outer_kernel()
{
    __shared__ float Ks[32][68];
    __shared__ float Vs[32][68];

    const int t  = threadIdx.x;
    const int tx = t & 15;
    const int ty = t >> 4;
    const int b  = blockIdx.y;
    const int s0 = blockIdx.x * CS;

    const float4* K4 = (const float4*)(g_K + ((size_t)b * TT + s0) * HH);
    const float4* V4 = (const float4*)(g_V + ((size_t)b * TT + s0) * HH);

    float acc[4][4];
#pragma unroll
    for (int i = 0; i < 4; i++)
#pragma unroll
        for (int j = 0; j < 4; j++) acc[i][j] = 0.f;

#pragma unroll
    for (int l = 0; l < 2; l++) {
        int f   = t + l * 256;
        int row = f >> 4;
        int c4  = f & 15;
        float4 kv = K4[(size_t)row * 16 + c4];
        float4 vv = V4[(size_t)row * 16 + c4];
        *(float4*)&Ks[row][c4 * 4] = kv;
        *(float4*)&Vs[row][c4 * 4] = vv;
    }
    __syncthreads();

#pragma unroll 8
    for (int s = 0; s < 32; s++) {
        float4 a4 = *(const float4*)&Ks[s][ty * 4];
        float4 b4 = *(const float4*)&Vs[s][tx * 4];
        float a[4] = {a4.x, a4.y, a4.z, a4.w};
        float bb2[4] = {b4.x, b4.y, b4.z, b4.w};
#pragma unroll
        for (int i = 0; i < 4; i++)
#pragma unroll
            for (int j = 0; j < 4; j++)
                acc[i][j] += a[i] * bb2[j];
    }

    float* Mb = g_M + (size_t)b * HH * HH;
#pragma unroll
    for (int i = 0; i < 4; i++)
#pragma unroll
        for (int j = 0; j < 4; j++)
            atomicAdd(&Mb[(ty * 4 + i) * HH + tx * 4 + j], acc[i][j]);
}

// ---------------------------------------------------------------------------
// out[b] = SCALE * Q[b] @ M[b]
// ---------------------------------------------------------------------------
__global__ __launch_bounds__(256) void out_kernel(float* __restrict__ out)
{
    __shared__ float Ms[64][68];
    __shared__ float Qs[64][68];

    const int t    = threadIdx.x;
    const int tx   = t & 15;
    const int ty   = t >> 4;
    const int row0 = blockIdx.x * 64;
    const int b    = row0 / TT;

    const float4* Q4 = (const float4*)(g_Q + (size_t)row0 * HH);
    const float4* M4 = (const float4*)(g_M + (size_t)b * HH * HH);

#pragma unroll
    for (int l = 0; l < 4; l++) {
        int f   = t + l * 256;
        int row = f >> 4;
        int c4  = f & 15;
        float4 qv = Q4[(size_t)row * 16 + c4];
        float4 mv = M4[(size_t)row * 16 + c4];
        *(float4*)&Qs[row][c4 * 4] = qv;
        *(float4*)&Ms[row][c4 * 4] = mv;
    }
    __syncthreads();

    float acc[4][4];
#pragma unroll
    for (int i = 0; i < 4; i++)
#pragma unroll
        for (int j = 0; j < 4; j++) acc[i][j] = 0.f;

#pragma unroll 4
    for (int k0 = 0; k0 < 64; k0 += 4) {
        float4 q4[4];
#pragma unroll
        for (int i = 0; i < 4; i++)
            q4[i] = *(const float4*)&Qs[ty * 4 + i][k0];
#pragma unroll
        for (int kk = 0; kk < 4; kk++) {
            float4 m4 = *(const float4*)&Ms[k0 + kk][tx * 4];
            float m[4] = {m4.x, m4.y, m4.z, m4.w};
#pragma unroll
            for (int i = 0; i < 4; i++) {
                float qv = (kk == 0) ? q4[i].x : (kk == 1) ? q4[i].y
                         : (kk == 2) ? q4[i].z : q4[i].w;
#pragma unroll
                for (int j = 0; j < 4; j++)
                    acc[i][j] += qv * m[j];
            }
        }
    }

#pragma unroll
    for (int i = 0; i < 4; i++) {
        int r = row0 + ty * 4 + i;
        float4 o;
        o.x = acc[i][0] * SCALE;
        o.y = acc[i][1] * SCALE;
        o.z = acc[i][2] * SCALE;
        o.w = acc[i][3] * SCALE;
        *(float4*)&out[(size_t)r * HH + tx * 4] = o;
    }
}

// ---------------------------------------------------------------------------
// Launch
// ---------------------------------------------------------------------------
extern "C" void kernel_launch(void* const* d_in, const int* in_sizes, int n_in,
                              void* d_out, int out_size)
{
    const float* idx = (const float*)d_in[0];
    const float* Wq  = (const float*)d_in[1];
    const float* bq  = (const float*)d_in[2];
    const float* Wk  = (const float*)d_in[3];
    const float* bk  = (const float*)d_in[4];
    const float* Wv  = (const float*)d_in[5];
    const float* bv  = (const float*)d_in[6];
    float* out = (float*)d_out;

    static bool attr_set = false;
    if (!attr_set) {
        cudaFuncSetAttribute(qkv_mma_kernel,
                             cudaFuncAttributeMaxDynamicSharedMemorySize, QKV_SMEM);
        attr_set = true;
    }

    prep_kernel<<<(192 * EE + 255) / 256, 256>>>(Wq, Wk, Wv);

    qkv_mma_kernel<<<BT / 64, 256, QKV_SMEM>>>(idx, bq, bk, bv);

    kv_outer_kernel<<<dim3(TT / CS, BB), 256>>>();

    out_kernel<<<BT / 64, 256>>>(out);
}